// round 13
// baseline (speedup 1.0000x reference)
#include <cuda_runtime.h>
#include <cuda_bf16.h>
#include <math.h>
#include <float.h>

#define NN   50000
#define DD   128
#define NE   800000
#define TOTF (NN * DD)          // 6,400,000
#define NBLK 196                // ceil(NN/256)
#define NSLOT 32

#define GEMM_SMEM  ((2*128*36 + 2*32*132) * 4)   // 70656 bytes

// ---------------- scratch (static device globals only) ----------------
__device__ uint2  g_xwb[TOTF / 4];   // bf16x4: GCN pre-scaled features (gather src)
__device__ uint2  g_xlb[TOTF / 4];   // bf16x4: GAT xl features (gather src)
__device__ uint2  g_h1b[TOTF / 4];   // bf16x4: hidden 1
__device__ uint2  g_h2b[TOTF / 4];   // bf16x4: hidden 2
__device__ uint2  g_xrb[TOTF / 4];   // bf16x4: GAT xr
__device__ float  g_dinv[NN];
__device__ int    g_cnt[NN];
__device__ int    g_ptr[NN + 1];
__device__ int    g_ptr2[NN];
__device__ int    g_csr_src[NE];
__device__ int    g_bsum[NBLK];
__device__ int    g_arrive;
__device__ double g_stats[4][NSLOT * 2];

// ---------------- helpers ----------------
__device__ __forceinline__ float lrelu(float x) { return x > 0.f ? x : 0.2f * x; }

__device__ __forceinline__ unsigned f2tf(float x) {
    unsigned u; asm("cvt.rna.tf32.f32 %0, %1;" : "=r"(u) : "f"(x)); return u;
}

__device__ __forceinline__ unsigned pack_bf2(float a, float b) {
    __nv_bfloat162 h = __floats2bfloat162_rn(a, b);
    return *(unsigned*)&h;
}

__device__ __forceinline__ uint2 pack_bf4(float4 v) {
    return make_uint2(pack_bf2(v.x, v.y), pack_bf2(v.z, v.w));
}

__device__ __forceinline__ float4 bf4_to_f4(uint2 u) {
    __nv_bfloat162 a = *(__nv_bfloat162*)&u.x;
    __nv_bfloat162 b = *(__nv_bfloat162*)&u.y;
    return make_float4(__low2float(a), __high2float(a), __low2float(b), __high2float(b));
}

__device__ __forceinline__ void mma_tf32(float* d, const unsigned* a, const unsigned* b) {
    asm volatile("mma.sync.aligned.m16n8k8.row.col.f32.tf32.tf32.f32 "
                 "{%0,%1,%2,%3}, {%4,%5,%6,%7}, {%8,%9}, {%0,%1,%2,%3};"
                 : "+f"(d[0]), "+f"(d[1]), "+f"(d[2]), "+f"(d[3])
                 : "r"(a[0]), "r"(a[1]), "r"(a[2]), "r"(a[3]),
                   "r"(b[0]), "r"(b[1]));
}

__device__ __forceinline__ void stats_from_slots(const double* slot, float* mi) {
    double s = 0.0, sq = 0.0;
#pragma unroll
    for (int i = 0; i < NSLOT; i++) { s += slot[2 * i]; sq += slot[2 * i + 1]; }
    double m   = s / (double)TOTF;
    double var = sq / (double)TOTF - m * m;
    mi[0] = (float)m;
    mi[1] = 1.f / ((float)sqrt(fmax(var, 0.0)) + 1e-5f);
}

// ---------------- init / CSR (R8-proven path) ----------------
__global__ void init_zero_kernel() {
    int i = blockIdx.x * blockDim.x + threadIdx.x;
    if (i < NN) g_cnt[i] = 0;
    if (i < 4 * NSLOT * 2) ((double*)g_stats)[i] = 0.0;
    if (i == 0) g_arrive = 0;
}
__global__ void hist_kernel(const int* __restrict__ dst) {
    int e = blockIdx.x * blockDim.x + threadIdx.x;
    if (e < NE) atomicAdd(&g_cnt[dst[e]], 1);
}
__global__ void scan_fused_kernel() {
    __shared__ int sh[256];
    int b = blockIdx.x;
    int i = b * 256 + threadIdx.x;
    int cnt = (i < NN) ? g_cnt[i] : 0;
    sh[threadIdx.x] = cnt;
    __syncthreads();
#pragma unroll
    for (int off = 1; off < 256; off <<= 1) {
        int t = (threadIdx.x >= off) ? sh[threadIdx.x - off] : 0;
        __syncthreads();
        sh[threadIdx.x] += t;
        __syncthreads();
    }
    int incl = sh[threadIdx.x];
    if (threadIdx.x == 0) {
        g_bsum[b] = sh[255];
        __threadfence();
        atomicAdd(&g_arrive, 1);
        while (atomicAdd(&g_arrive, 0) < NBLK) { }
    }
    __syncthreads();
    int p = 0;
    for (int j = threadIdx.x; j < b; j += 256) p += g_bsum[j];
    sh[threadIdx.x] = p;
    __syncthreads();
#pragma unroll
    for (int o = 128; o > 0; o >>= 1) {
        if (threadIdx.x < o) sh[threadIdx.x] += sh[threadIdx.x + o];
        __syncthreads();
    }
    int base = sh[0];
    if (i < NN) {
        int excl = base + incl - cnt;
        g_ptr[i]  = excl;
        g_ptr2[i] = excl;
        g_dinv[i] = rsqrtf((float)(cnt + 1));
    }
    if (i == 0) g_ptr[NN] = NE;
}
__global__ void scatter_kernel(const int* __restrict__ src, const int* __restrict__ dst) {
    int e = blockIdx.x * blockDim.x + threadIdx.x;
    if (e >= NE) return;
    int pos = atomicAdd(&g_ptr2[dst[e]], 1);
    g_csr_src[pos] = src[e];
}

// ---------------- TF32 GEMM N=128 (A fp32 or bf16): Cbf16 = rowscale*(nr(A)@W)
template <int ABF16>
__global__ __launch_bounds__(256, 2)
void gemm_tf32_kernel(const void* __restrict__ Avoid, const float* __restrict__ W,
                      unsigned* __restrict__ Cb, int M,
                      const float* __restrict__ gamma, const float* __restrict__ beta,
                      const double* __restrict__ slot, const float* __restrict__ rowscale)
{
    extern __shared__ unsigned smem_raw[];
    unsigned (*As)[128][36] = (unsigned (*)[128][36])smem_raw;
    unsigned (*Bs)[32][132] = (unsigned (*)[32][132])(smem_raw + 2 * 128 * 36);
    __shared__ float s_mi[2];
    const float* Af = (const float*)Avoid;
    const uint2* Ab = (const uint2*)Avoid;

    int tid  = threadIdx.x;
    int wid  = tid >> 5, lane = tid & 31;
    int wm   = wid & 3, wn = wid >> 2;
    int m0   = blockIdx.x * 128;

    if (tid == 0) {
        if (slot) stats_from_slots(slot, s_mi);
        else { s_mi[0] = 0.f; s_mi[1] = 1.f; }
    }
    __syncthreads();
    float mu = s_mi[0], inv = s_mi[1];
    bool donorm = (slot != nullptr);

    float acc[2][8][4];
#pragma unroll
    for (int i = 0; i < 2; i++)
#pragma unroll
        for (int j = 0; j < 8; j++)
#pragma unroll
            for (int q = 0; q < 4; q++) acc[i][j][q] = 0.f;

    int Ar[4], Aq[4], Br[4], Bq[4];
#pragma unroll
    for (int i = 0; i < 4; i++) {
        int lin = tid + i * 256;
        Ar[i] = lin >> 3;  Aq[i] = (lin & 7) * 4;
        Br[i] = lin >> 5;  Bq[i] = (lin & 31) * 4;
    }
    float4 ra[4], rb[4];

#define LOAD_TILE(k0)                                                              \
    {                                                                              \
        _Pragma("unroll")                                                          \
        for (int i = 0; i < 4; i++) {                                              \
            if (m0 + Ar[i] < M) {                                                  \
                if (ABF16) {                                                       \
                    uint2 u = Ab[(size_t)(m0 + Ar[i]) * 32 + (((k0) + Aq[i]) >> 2)];\
                    ra[i] = bf4_to_f4(u);                                          \
                } else                                                             \
                    ra[i] = *(const float4*)(Af + (size_t)(m0 + Ar[i]) * 128       \
                                             + (k0) + Aq[i]);                      \
            } else ra[i] = make_float4(0.f, 0.f, 0.f, 0.f);                        \
            rb[i] = *(const float4*)(W + (size_t)((k0) + Br[i]) * 128 + Bq[i]);    \
        }                                                                          \
    }
#define STORE_TILE(buf, k0)                                                        \
    {                                                                              \
        _Pragma("unroll")                                                          \
        for (int i = 0; i < 4; i++) {                                              \
            float4 v = ra[i];                                                      \
            if (donorm) {                                                          \
                float4 gv = *(const float4*)(gamma + (k0) + Aq[i]);                \
                float4 bv = *(const float4*)(beta  + (k0) + Aq[i]);                \
                v.x = fmaxf((v.x - mu) * inv * gv.x + bv.x, 0.f);                  \
                v.y = fmaxf((v.y - mu) * inv * gv.y + bv.y, 0.f);                  \
                v.z = fmaxf((v.z - mu) * inv * gv.z + bv.z, 0.f);                  \
                v.w = fmaxf((v.w - mu) * inv * gv.w + bv.w, 0.f);                  \
            }                                                                      \
            As[buf][Ar[i]][Aq[i] + 0] = f2tf(v.x);                                 \
            As[buf][Ar[i]][Aq[i] + 1] = f2tf(v.y);                                 \
            As[buf][Ar[i]][Aq[i] + 2] = f2tf(v.z);                                 \
            As[buf][Ar[i]][Aq[i] + 3] = f2tf(v.w);                                 \
            Bs[buf][Br[i]][Bq[i] + 0] = f2tf(rb[i].x);                             \
            Bs[buf][Br[i]][Bq[i] + 1] = f2tf(rb[i].y);                             \
            Bs[buf][Br[i]][Bq[i] + 2] = f2tf(rb[i].z);                             \
            Bs[buf][Br[i]][Bq[i] + 3] = f2tf(rb[i].w);                             \
        }                                                                          \
    }
#define COMPUTE(buf)                                                               \
    {                                                                              \
        _Pragma("unroll")                                                          \
        for (int kk = 0; kk < 32; kk += 8) {                                       \
            unsigned a[2][4], b[8][2];                                             \
            int ar = wm * 32 + (lane >> 2);                                        \
            int ak = kk + (lane & 3);                                              \
            a[0][0] = As[buf][ar][ak];          a[0][1] = As[buf][ar + 8][ak];     \
            a[0][2] = As[buf][ar][ak + 4];      a[0][3] = As[buf][ar + 8][ak + 4]; \
            a[1][0] = As[buf][ar + 16][ak];     a[1][1] = As[buf][ar + 24][ak];    \
            a[1][2] = As[buf][ar + 16][ak + 4]; a[1][3] = As[buf][ar + 24][ak + 4];\
            _Pragma("unroll")                                                      \
            for (int j = 0; j < 8; j++) {                                          \
                int col = wn * 64 + j * 8 + (lane >> 2);                           \
                b[j][0] = Bs[buf][kk + (lane & 3)][col];                           \
                b[j][1] = Bs[buf][kk + 4 + (lane & 3)][col];                       \
            }                                                                      \
            _Pragma("unroll")                                                      \
            for (int i = 0; i < 2; i++)                                            \
                _Pragma("unroll")                                                  \
                for (int j = 0; j < 8; j++) mma_tf32(acc[i][j], a[i], b[j]);       \
        }                                                                          \
    }

    LOAD_TILE(0);
    STORE_TILE(0, 0);
    __syncthreads();
#pragma unroll
    for (int t = 0; t < 4; t++) {
        if (t < 3) LOAD_TILE((t + 1) * 32);
        COMPUTE(t & 1);
        if (t < 3) { STORE_TILE((t + 1) & 1, (t + 1) * 32); __syncthreads(); }
    }

#pragma unroll
    for (int i = 0; i < 2; i++) {
#pragma unroll
        for (int j = 0; j < 8; j++) {
            int r0 = m0 + wm * 32 + i * 16 + (lane >> 2);
            int cc = wn * 64 + j * 8 + (lane & 3) * 2;
            if (r0 < M) {
                float sc = rowscale[r0];
                Cb[(size_t)r0 * 64 + (cc >> 1)] = pack_bf2(acc[i][j][0] * sc, acc[i][j][1] * sc);
            }
            if (r0 + 8 < M) {
                float sc = rowscale[r0 + 8];
                Cb[(size_t)(r0 + 8) * 64 + (cc >> 1)] = pack_bf2(acc[i][j][2] * sc, acc[i][j][3] * sc);
            }
        }
    }
#undef LOAD_TILE
#undef STORE_TILE
#undef COMPUTE
}

// ---------------- GAT GEMM: one launch, 2*GRID halves (xl | xr), A bf16 -------
__global__ __launch_bounds__(256, 2)
void gemm_gat2_kernel(const uint2* __restrict__ Ab,
                      const float* __restrict__ Wl, const float* __restrict__ bl,
                      const float* __restrict__ Wr, const float* __restrict__ br,
                      unsigned* __restrict__ XLb, unsigned* __restrict__ XRb,
                      int M, int gridHalf,
                      const float* __restrict__ gamma, const float* __restrict__ beta,
                      const double* __restrict__ slot)
{
    extern __shared__ unsigned smem_raw[];
    unsigned (*As)[128][36] = (unsigned (*)[128][36])smem_raw;
    unsigned (*Bs)[32][132] = (unsigned (*)[32][132])(smem_raw + 2 * 128 * 36);
    __shared__ float s_mi[2];

    int half = (blockIdx.x >= gridHalf) ? 1 : 0;
    const float* W   = half ? Wr : Wl;
    const float* bia = half ? br : bl;
    unsigned*    Cb  = half ? XRb : XLb;
    int m0 = (blockIdx.x - half * gridHalf) * 128;

    int tid  = threadIdx.x;
    int wid  = tid >> 5, lane = tid & 31;
    int wm   = wid & 3, wn = wid >> 2;

    if (tid == 0) stats_from_slots(slot, s_mi);
    __syncthreads();
    float mu = s_mi[0], inv = s_mi[1];

    float acc[2][8][4];
#pragma unroll
    for (int i = 0; i < 2; i++)
#pragma unroll
        for (int j = 0; j < 8; j++)
#pragma unroll
            for (int q = 0; q < 4; q++) acc[i][j][q] = 0.f;

    int Ar[4], Aq[4], Br_[4], Bq[4];
#pragma unroll
    for (int i = 0; i < 4; i++) {
        int lin = tid + i * 256;
        Ar[i]  = lin >> 3;  Aq[i] = (lin & 7) * 4;
        Br_[i] = lin >> 5;  Bq[i] = (lin & 31) * 4;
    }
    float4 ra[4], rb[4];

#define LOAD_TILE(k0)                                                              \
    {                                                                              \
        _Pragma("unroll")                                                          \
        for (int i = 0; i < 4; i++) {                                              \
            if (m0 + Ar[i] < M) {                                                  \
                uint2 u = Ab[(size_t)(m0 + Ar[i]) * 32 + (((k0) + Aq[i]) >> 2)];   \
                ra[i] = bf4_to_f4(u);                                              \
            } else ra[i] = make_float4(0.f, 0.f, 0.f, 0.f);                        \
            rb[i] = *(const float4*)(W + (size_t)((k0) + Br_[i]) * 128 + Bq[i]);   \
        }                                                                          \
    }
#define STORE_TILE(buf, k0)                                                        \
    {                                                                              \
        _Pragma("unroll")                                                          \
        for (int i = 0; i < 4; i++) {                                              \
            float4 v = ra[i];                                                      \
            float4 gv = *(const float4*)(gamma + (k0) + Aq[i]);                    \
            float4 bv = *(const float4*)(beta  + (k0) + Aq[i]);                    \
            v.x = fmaxf((v.x - mu) * inv * gv.x + bv.x, 0.f);                      \
            v.y = fmaxf((v.y - mu) * inv * gv.y + bv.y, 0.f);                      \
            v.z = fmaxf((v.z - mu) * inv * gv.z + bv.z, 0.f);                      \
            v.w = fmaxf((v.w - mu) * inv * gv.w + bv.w, 0.f);                      \
            As[buf][Ar[i]][Aq[i] + 0] = f2tf(v.x);                                 \
            As[buf][Ar[i]][Aq[i] + 1] = f2tf(v.y);                                 \
            As[buf][Ar[i]][Aq[i] + 2] = f2tf(v.z);                                 \
            As[buf][Ar[i]][Aq[i] + 3] = f2tf(v.w);                                 \
            Bs[buf][Br_[i]][Bq[i] + 0] = f2tf(rb[i].x);                            \
            Bs[buf][Br_[i]][Bq[i] + 1] = f2tf(rb[i].y);                            \
            Bs[buf][Br_[i]][Bq[i] + 2] = f2tf(rb[i].z);                            \
            Bs[buf][Br_[i]][Bq[i] + 3] = f2tf(rb[i].w);                            \
        }                                                                          \
    }
#define COMPUTE(buf)                                                               \
    {                                                                              \
        _Pragma("unroll")                                                          \
        for (int kk = 0; kk < 32; kk += 8) {                                       \
            unsigned a[2][4], b[8][2];                                             \
            int ar = wm * 32 + (lane >> 2);                                        \
            int ak = kk + (lane & 3);                                              \
            a[0][0] = As[buf][ar][ak];          a[0][1] = As[buf][ar + 8][ak];     \
            a[0][2] = As[buf][ar][ak + 4];      a[0][3] = As[buf][ar + 8][ak + 4]; \
            a[1][0] = As[buf][ar + 16][ak];     a[1][1] = As[buf][ar + 24][ak];    \
            a[1][2] = As[buf][ar + 16][ak + 4]; a[1][3] = As[buf][ar + 24][ak + 4];\
            _Pragma("unroll")                                                      \
            for (int j = 0; j < 8; j++) {                                          \
                int col = wn * 64 + j * 8 + (lane >> 2);                           \
                b[j][0] = Bs[buf][kk + (lane & 3)][col];                           \
                b[j][1] = Bs[buf][kk + 4 + (lane & 3)][col];                       \
            }                                                                      \
            _Pragma("unroll")                                                      \
            for (int i = 0; i < 2; i++)                                            \
                _Pragma("unroll")                                                  \
                for (int j = 0; j < 8; j++) mma_tf32(acc[i][j], a[i], b[j]);       \
        }                                                                          \
    }

    LOAD_TILE(0);
    STORE_TILE(0, 0);
    __syncthreads();
#pragma unroll
    for (int t = 0; t < 4; t++) {
        if (t < 3) LOAD_TILE((t + 1) * 32);
        COMPUTE(t & 1);
        if (t < 3) { STORE_TILE((t + 1) & 1, (t + 1) * 32); __syncthreads(); }
    }

#pragma unroll
    for (int i = 0; i < 2; i++) {
#pragma unroll
        for (int j = 0; j < 8; j++) {
            int r0 = m0 + wm * 32 + i * 16 + (lane >> 2);
            int cc = wn * 64 + j * 8 + (lane & 3) * 2;
            float b0 = bia[cc], b1 = bia[cc + 1];
            if (r0 < M)
                Cb[(size_t)r0 * 64 + (cc >> 1)] = pack_bf2(acc[i][j][0] + b0, acc[i][j][1] + b1);
            if (r0 + 8 < M)
                Cb[(size_t)(r0 + 8) * 64 + (cc >> 1)] = pack_bf2(acc[i][j][2] + b0, acc[i][j][3] + b1);
        }
    }
#undef LOAD_TILE
#undef STORE_TILE
#undef COMPUTE
}

// ---------------- block stat reduce (full block, no early exits) -------
__device__ __forceinline__ void accum_stats(float4 o, int lane, int tid, double* slot)
{
    float s  = o.x + o.y + o.z + o.w;
    float sq = o.x * o.x + o.y * o.y + o.z * o.z + o.w * o.w;
#pragma unroll
    for (int off = 16; off > 0; off >>= 1) {
        s  += __shfl_xor_sync(0xffffffffu, s,  off);
        sq += __shfl_xor_sync(0xffffffffu, sq, off);
    }
    __shared__ float bs[2];
    if (tid == 0) { bs[0] = 0.f; bs[1] = 0.f; }
    __syncthreads();
    if (lane == 0) { atomicAdd(&bs[0], s); atomicAdd(&bs[1], sq); }
    __syncthreads();
    if (tid == 0) {
        int sl = blockIdx.x & (NSLOT - 1);
        atomicAdd(&slot[2 * sl],     (double)bs[0]);
        atomicAdd(&slot[2 * sl + 1], (double)bs[1]);
    }
}

// ---------------- GCN gather (warp per node, bf16 in, bf16 out) ---------------
__global__ void gcn_gather_kernel(const float* __restrict__ bias,
                                  uint2* __restrict__ outb, double* __restrict__ slot)
{
    int tid  = threadIdx.x;
    int lane = tid & 31;
    int n = (blockIdx.x * blockDim.x + tid) >> 5;   // grid exact: NN/8 blocks
    int c = lane * 4;

    float4 acc = bf4_to_f4(g_xwb[(size_t)n * 32 + lane]);   // self (pre-scaled)

    int e = g_ptr[n], end = g_ptr[n + 1];
    for (; e + 7 < end; e += 8) {
        int s[8];
#pragma unroll
        for (int i = 0; i < 8; i++) s[i] = g_csr_src[e + i];
        uint2 u[8];
#pragma unroll
        for (int i = 0; i < 8; i++) u[i] = g_xwb[(size_t)s[i] * 32 + lane];
#pragma unroll
        for (int i = 0; i < 8; i++) {
            float4 v = bf4_to_f4(u[i]);
            acc.x += v.x; acc.y += v.y; acc.z += v.z; acc.w += v.w;
        }
    }
    for (; e + 3 < end; e += 4) {
        uint2 u0 = g_xwb[(size_t)g_csr_src[e] * 32 + lane];
        uint2 u1 = g_xwb[(size_t)g_csr_src[e + 1] * 32 + lane];
        uint2 u2 = g_xwb[(size_t)g_csr_src[e + 2] * 32 + lane];
        uint2 u3 = g_xwb[(size_t)g_csr_src[e + 3] * 32 + lane];
        float4 v0 = bf4_to_f4(u0), v1 = bf4_to_f4(u1);
        float4 v2 = bf4_to_f4(u2), v3 = bf4_to_f4(u3);
        acc.x += (v0.x + v1.x) + (v2.x + v3.x);
        acc.y += (v0.y + v1.y) + (v2.y + v3.y);
        acc.z += (v0.z + v1.z) + (v2.z + v3.z);
        acc.w += (v0.w + v1.w) + (v2.w + v3.w);
    }
    for (; e < end; e++) {
        float4 v = bf4_to_f4(g_xwb[(size_t)g_csr_src[e] * 32 + lane]);
        acc.x += v.x; acc.y += v.y; acc.z += v.z; acc.w += v.w;
    }
    float dn = g_dinv[n];
    float4 bv = *(const float4*)(bias + c);
    acc.x = acc.x * dn + bv.x;
    acc.y = acc.y * dn + bv.y;
    acc.z = acc.z * dn + bv.z;
    acc.w = acc.w * dn + bv.w;
    outb[(size_t)n * 32 + lane] = pack_bf4(acc);
    accum_stats(acc, lane, tid, slot);
}

// ---------------- fused GATv2 gather; H=8 -> bf16 out, H=1 -> fp32 out --------
template <int H, int OUTF32>
__global__ void gat_gather_kernel(const float* __restrict__ att, const float* __restrict__ bg,
                                  float* __restrict__ outf, uint2* __restrict__ outb,
                                  double* __restrict__ slot)
{
    int tid  = threadIdx.x;
    int lane = tid & 31;
    int n = (blockIdx.x * blockDim.x + tid) >> 5;
    int c = lane * 4;

    float4 xrd = bf4_to_f4(g_xrb[(size_t)n * 32 + lane]);
    float4 w4  = *(const float4*)(att + c);

    float m = -FLT_MAX, ssum = 0.f;
    float4 acc = make_float4(0.f, 0.f, 0.f, 0.f);

#define GAT_SCORE(v, p)                                                            \
    p = w4.x * lrelu((v).x + xrd.x) + w4.y * lrelu((v).y + xrd.y)                  \
      + w4.z * lrelu((v).z + xrd.z) + w4.w * lrelu((v).w + xrd.w);

#define GAT_PROC1(v)                                                               \
    {                                                                              \
        float p; GAT_SCORE(v, p);                                                  \
        _Pragma("unroll")                                                          \
        for (int off = 1; off < 32 / H; off <<= 1)                                 \
            p += __shfl_xor_sync(0xffffffffu, p, off);                             \
        float mn = fmaxf(m, p);                                                    \
        float sc = __expf(m - mn);                                                 \
        float wg = __expf(p - mn);                                                 \
        ssum = ssum * sc + wg;                                                     \
        acc.x = acc.x * sc + wg * (v).x;                                           \
        acc.y = acc.y * sc + wg * (v).y;                                           \
        acc.z = acc.z * sc + wg * (v).z;                                           \
        acc.w = acc.w * sc + wg * (v).w;                                           \
        m = mn;                                                                    \
    }

    {
        float4 v = bf4_to_f4(g_xlb[(size_t)n * 32 + lane]);   // self loop
        GAT_PROC1(v);
    }
    int e = g_ptr[n], end = g_ptr[n + 1];
    for (; e + 3 < end; e += 4) {
        uint2 u0 = g_xlb[(size_t)g_csr_src[e] * 32 + lane];
        uint2 u1 = g_xlb[(size_t)g_csr_src[e + 1] * 32 + lane];
        uint2 u2 = g_xlb[(size_t)g_csr_src[e + 2] * 32 + lane];
        uint2 u3 = g_xlb[(size_t)g_csr_src[e + 3] * 32 + lane];
        float4 v0 = bf4_to_f4(u0), v1 = bf4_to_f4(u1);
        float4 v2 = bf4_to_f4(u2), v3 = bf4_to_f4(u3);
        float p0, p1, p2, p3;
        GAT_SCORE(v0, p0); GAT_SCORE(v1, p1); GAT_SCORE(v2, p2); GAT_SCORE(v3, p3);
#pragma unroll
        for (int off = 1; off < 32 / H; off <<= 1) {
            p0 += __shfl_xor_sync(0xffffffffu, p0, off);
            p1 += __shfl_xor_sync(0xffffffffu, p1, off);
            p2 += __shfl_xor_sync(0xffffffffu, p2, off);
            p3 += __shfl_xor_sync(0xffffffffu, p3, off);
        }
        float bm = fmaxf(fmaxf(p0, p1), fmaxf(p2, p3));
        float mn = fmaxf(m, bm);
        float sc = __expf(m - mn);
        float w0 = __expf(p0 - mn), w1 = __expf(p1 - mn);
        float w2 = __expf(p2 - mn), w3 = __expf(p3 - mn);
        ssum = ssum * sc + ((w0 + w1) + (w2 + w3));
        acc.x = acc.x * sc + (w0 * v0.x + w1 * v1.x) + (w2 * v2.x + w3 * v3.x);
        acc.y = acc.y * sc + (w0 * v0.y + w1 * v1.y) + (w2 * v2.y + w3 * v3.y);
        acc.z = acc.z * sc + (w0 * v0.z + w1 * v1.z) + (w2 * v2.z + w3 * v3.z);
        acc.w = acc.w * sc + (w0 * v0.w + w1 * v1.w) + (w2 * v2.w + w3 * v3.w);
        m = mn;
    }
    for (; e < end; e++) {
        float4 v = bf4_to_f4(g_xlb[(size_t)g_csr_src[e] * 32 + lane]);
        GAT_PROC1(v);
    }
#undef GAT_PROC1
#undef GAT_SCORE

    float inv = 1.f / ssum;
    float4 bv = *(const float4*)(bg + c);
    float4 o;
    o.x = acc.x * inv + bv.x;
    o.y = acc.y * inv + bv.y;
    o.z = acc.z * inv + bv.z;
    o.w = acc.w * inv + bv.w;
    if (OUTF32) *(float4*)(outf + (size_t)n * 128 + c) = o;
    else        outb[(size_t)n * 32 + lane] = pack_bf4(o);
    accum_stats(o, lane, tid, slot);
}

// ---------------- final LayerNorm ----------------
__global__ void ln_final_kernel(float* __restrict__ x, const float* __restrict__ g,
                                const float* __restrict__ b, const double* __restrict__ slot)
{
    __shared__ float s_mi[2];
    if (threadIdx.x == 0) stats_from_slots(slot, s_mi);
    __syncthreads();
    float mu = s_mi[0], inv = s_mi[1];
    int i = (blockIdx.x * blockDim.x + threadIdx.x) * 4;
    int c = i & 127;
    float4 v  = *(const float4*)(x + i);
    float4 gv = *(const float4*)(g + c);
    float4 bv = *(const float4*)(b + c);
    v.x = (v.x - mu) * inv * gv.x + bv.x;
    v.y = (v.y - mu) * inv * gv.y + bv.y;
    v.z = (v.z - mu) * inv * gv.z + bv.z;
    v.w = (v.w - mu) * inv * gv.w + bv.w;
    *(float4*)(x + i) = v;
}

// ---------------- host orchestration ----------------
extern "C" void kernel_launch(void* const* d_in, const int* in_sizes, int n_in,
                              void* d_out, int out_size)
{
    const float* x    = (const float*)d_in[0];
    const int*   ei   = (const int*)  d_in[1];
    const float* W0   = (const float*)d_in[2];
    const float* b0   = (const float*)d_in[3];
    const float* g0   = (const float*)d_in[4];
    const float* be0  = (const float*)d_in[5];
    const float* Wl1  = (const float*)d_in[6];
    const float* bl1  = (const float*)d_in[7];
    const float* Wr1  = (const float*)d_in[8];
    const float* br1  = (const float*)d_in[9];
    const float* att1 = (const float*)d_in[10];
    const float* bg1  = (const float*)d_in[11];
    const float* g1   = (const float*)d_in[12];
    const float* be1  = (const float*)d_in[13];
    const float* W2   = (const float*)d_in[14];
    const float* b2   = (const float*)d_in[15];
    const float* g2   = (const float*)d_in[16];
    const float* be2  = (const float*)d_in[17];
    const float* Wl3  = (const float*)d_in[18];
    const float* bl3  = (const float*)d_in[19];
    const float* Wr3  = (const float*)d_in[20];
    const float* br3  = (const float*)d_in[21];
    const float* att3 = (const float*)d_in[22];
    const float* bg3  = (const float*)d_in[23];
    const float* g3   = (const float*)d_in[24];
    const float* be3  = (const float*)d_in[25];

    const int* src = ei;
    const int* dst = ei + NE;
    float* out = (float*)d_out;

    float* dinv;
    uint2 *xwb, *xlb, *h1b, *h2b, *xrb;
    double* st;
    cudaGetSymbolAddress((void**)&xwb, g_xwb);
    cudaGetSymbolAddress((void**)&xlb, g_xlb);
    cudaGetSymbolAddress((void**)&h1b, g_h1b);
    cudaGetSymbolAddress((void**)&h2b, g_h2b);
    cudaGetSymbolAddress((void**)&xrb, g_xrb);
    cudaGetSymbolAddress((void**)&dinv, g_dinv);
    cudaGetSymbolAddress((void**)&st, g_stats);
    double* s0 = st;
    double* s1 = st + NSLOT * 2;
    double* s2 = st + NSLOT * 4;
    double* s3 = st + NSLOT * 6;

    cudaFuncSetAttribute(gemm_tf32_kernel<0>,
                         cudaFuncAttributeMaxDynamicSharedMemorySize, GEMM_SMEM);
    cudaFuncSetAttribute(gemm_tf32_kernel<1>,
                         cudaFuncAttributeMaxDynamicSharedMemorySize, GEMM_SMEM);
    cudaFuncSetAttribute(gemm_gat2_kernel,
                         cudaFuncAttributeMaxDynamicSharedMemorySize, GEMM_SMEM);

    const int GEMM_GRID = (NN + 127) / 128;       // 391
    const int WARP_GRID = NN / 8;                 // 6250, exact

    // --- CSR build (R8-proven 4-launch path) ---
    init_zero_kernel<<<(NN + 255) / 256, 256>>>();
    hist_kernel<<<NE / 256, 256>>>(dst);
    scan_fused_kernel<<<NBLK, 256>>>();
    scatter_kernel<<<NE / 256, 256>>>(src, dst);

    // layer 0: GCN (x fp32), xw bf16 pre-scaled by dinv -> h1 bf16, stats s0
    gemm_tf32_kernel<0><<<GEMM_GRID, 256, GEMM_SMEM>>>(x, W0, (unsigned*)xwb, NN,
                                                       nullptr, nullptr, nullptr, dinv);
    gcn_gather_kernel<<<WARP_GRID, 256>>>(b0, h1b, s0);

    // layer 1: GATv2 H=8 (norm s0 + relu), xl/xr bf16 -> h2 bf16, stats s1
    gemm_gat2_kernel<<<2 * GEMM_GRID, 256, GEMM_SMEM>>>(h1b, Wl1, bl1, Wr1, br1,
                                                        (unsigned*)xlb, (unsigned*)xrb,
                                                        NN, GEMM_GRID, g0, be0, s0);
    gat_gather_kernel<8, 0><<<WARP_GRID, 256>>>(att1, bg1, nullptr, h2b, s1);

    // layer 2: GCN (norm s1 + relu, A bf16) -> h1 bf16, stats s2
    gemm_tf32_kernel<1><<<GEMM_GRID, 256, GEMM_SMEM>>>(h2b, W2, (unsigned*)xwb, NN,
                                                       g1, be1, s1, dinv);
    gcn_gather_kernel<<<WARP_GRID, 256>>>(b2, h1b, s2);

    // layer 3: GATv2 H=1 (norm s2 + relu, A bf16) -> out fp32, stats s3 -> final LN
    gemm_gat2_kernel<<<2 * GEMM_GRID, 256, GEMM_SMEM>>>(h1b, Wl3, bl3, Wr3, br3,
                                                        (unsigned*)xlb, (unsigned*)xrb,
                                                        NN, GEMM_GRID, g2, be2, s2);
    gat_gather_kernel<1, 1><<<WARP_GRID, 256>>>(att3, bg3, out, nullptr, s3);
    ln_final_kernel<<<TOTF / 1024, 256>>>(out, g3, be3, s3);
}